// round 8
// baseline (speedup 1.0000x reference)
#include <cuda_runtime.h>
#include <math.h>

#define NTOK  3072
#define UNITS 1024
#define NHEAD 16
#define HDIM  64
#define NBLK  64
#define CHK   32

// tf32-rounded operand pool: [x | Wq | Wk | Wv | Wo]
#define OFF_X  0
#define OFF_WQ (NTOK * UNITS)
#define OFF_WK (OFF_WQ + UNITS * UNITS)
#define OFF_WV (OFF_WK + UNITS * UNITS)
#define OFF_WO (OFF_WV + UNITS * UNITS)
#define TF_TOT (OFF_WO + UNITS * UNITS)

__device__ float g_tf[TF_TOT];
__device__ float g_QKV[3 * NTOK * UNITS];
__device__ float g_O[NTOK * UNITS];
__device__ int   g_cnt[NBLK];
__device__ int   g_off[NBLK];
__device__ int   g_mem[NTOK];

__device__ __forceinline__ unsigned f2tf32(float f) {
    unsigned u;
    asm("cvt.rna.tf32.f32 %0, %1;" : "=r"(u) : "f"(f));
    return u;
}

// ---------------------------------------------------------------------------
// Prep: round x + weights to tf32 once. 1835008 float4s = 7168 blocks x 256.
// ---------------------------------------------------------------------------
__global__ __launch_bounds__(256) void prep_kernel(
    const float* __restrict__ x,  const float* __restrict__ Wq,
    const float* __restrict__ Wk, const float* __restrict__ Wv,
    const float* __restrict__ Wo)
{
    int i = blockIdx.x * 256 + threadIdx.x;   // float4 index
    const float* src; int base;
    if      (i <  786432) { src = x;  base = 0;       }
    else if (i < 1048576) { src = Wq; base = 786432;  }
    else if (i < 1310720) { src = Wk; base = 1048576; }
    else if (i < 1572864) { src = Wv; base = 1310720; }
    else                  { src = Wo; base = 1572864; }
    float4 v = ((const float4*)src)[i - base];
    v.x = __uint_as_float(f2tf32(v.x));
    v.y = __uint_as_float(f2tf32(v.y));
    v.z = __uint_as_float(f2tf32(v.z));
    v.w = __uint_as_float(f2tf32(v.w));
    ((float4*)g_tf)[i] = v;
}

// ---------------------------------------------------------------------------
// Parallel index build: one warp per block id, order-preserving ballot ranks.
// ---------------------------------------------------------------------------
__global__ __launch_bounds__(32) void build_index_kernel(const int* __restrict__ ids) {
    int b    = blockIdx.x;
    int lane = threadIdx.x;
    int cnt = 0, off = 0;
    for (int i0 = 0; i0 < NTOK; i0 += 32) {
        int id = ids[i0 + lane];
        unsigned meq = __ballot_sync(0xFFFFFFFFu, id == b);
        unsigned mlt = __ballot_sync(0xFFFFFFFFu, id < b);
        cnt += __popc(meq);
        off += __popc(mlt);
    }
    if (lane == 0) { g_cnt[b] = cnt; g_off[b] = off; }
    int run = off;
    unsigned lmask = (1u << lane) - 1u;
    for (int i0 = 0; i0 < NTOK; i0 += 32) {
        int id = ids[i0 + lane];
        unsigned meq = __ballot_sync(0xFFFFFFFFu, id == b);
        if (id == b) g_mem[run + __popc(meq & lmask)] = i0 + lane;
        run += __popc(meq);
    }
}

// ---------------------------------------------------------------------------
// TF32 GEMM, cp.async 3-stage pipeline (round-6 proven path, unchanged).
// ---------------------------------------------------------------------------
#define STAGE_F 8192   // floats per stage (A 4096 + B 4096)

__device__ __forceinline__ void cp16(float* dst, const float* src) {
    unsigned d = (unsigned)__cvta_generic_to_shared(dst);
    asm volatile("cp.async.cg.shared.global [%0], [%1], 16;" :: "r"(d), "l"(src));
}

__device__ __forceinline__ void gemm_body(
    const float* __restrict__ A, const float* __restrict__ B,
    float* __restrict__ C, int NN, int K,
    float* smem, int rowBase, int colBase)
{
    const int t    = threadIdx.x;
    const int lane = t & 31;
    const int warp = t >> 5;
    const int wr   = warp >> 2;
    const int wc   = warp & 3;
    const int r    = lane >> 2;
    const int cq   = lane & 3;

    const int am  = t >> 1;
    const int ak0 = (t & 1) * 16;
    const float* Ag = A + (size_t)(rowBase + am) * K + ak0;
    int adst[4];
#pragma unroll
    for (int j = 0; j < 4; j++) {
        int kc = (t & 1) * 4 + j;
        adst[j] = am * 32 + ((kc ^ (am & 7)) * 4);
    }
    const int bkr  = t >> 3;
    const int bn40 = (t & 7) * 4;
    const float* Bg = B + (size_t)bkr * NN + colBase + bn40 * 4;
    int bdst[4];
#pragma unroll
    for (int j = 0; j < 4; j++) {
        int n4 = bn40 + j;
        bdst[j] = bkr * 128 + ((n4 ^ (2 * (bkr & 3))) * 4);
    }

    int a_b0[4], a_b8[4];
#pragma unroll
    for (int i = 0; i < 4; i++) {
        int m0 = wr * 64 + i * 16 + r;
        a_b0[i] = m0 * 32 + cq;
        a_b8[i] = (m0 + 8) * 32 + cq;
    }
    int b_n[4];
#pragma unroll
    for (int j = 0; j < 4; j++)
        b_n[j] = wc * 32 + ((j * 8 + r) ^ (8 * cq));

    float acc[4][4][4];
#pragma unroll
    for (int i = 0; i < 4; i++)
#pragma unroll
        for (int j = 0; j < 4; j++)
#pragma unroll
            for (int e = 0; e < 4; e++) acc[i][j][e] = 0.f;

    const int nT = K / 32;

#pragma unroll
    for (int pt = 0; pt < 2; pt++) {
        float* As = smem + pt * STAGE_F;
        float* Bs = As + 4096;
        const int ko = pt * 32;
#pragma unroll
        for (int j = 0; j < 4; j++) cp16(As + adst[j], Ag + ko + j * 4);
#pragma unroll
        for (int j = 0; j < 4; j++) cp16(Bs + bdst[j], Bg + (size_t)ko * NN + j * 4);
        asm volatile("cp.async.commit_group;" ::: "memory");
    }

    for (int tt = 0; tt < nT; tt++) {
        asm volatile("cp.async.wait_group 1;" ::: "memory");
        __syncthreads();

        if (tt + 2 < nT) {
            int st = (tt + 2) % 3;
            float* As = smem + st * STAGE_F;
            float* Bs = As + 4096;
            const int ko = (tt + 2) * 32;
#pragma unroll
            for (int j = 0; j < 4; j++) cp16(As + adst[j], Ag + ko + j * 4);
#pragma unroll
            for (int j = 0; j < 4; j++) cp16(Bs + bdst[j], Bg + (size_t)ko * NN + j * 4);
        }
        asm volatile("cp.async.commit_group;" ::: "memory");

        const float* As = smem + (tt % 3) * STAGE_F;
        const float* Bs = As + 4096;
#pragma unroll
        for (int ks = 0; ks < 4; ks++) {
            const int q0 = ((2 * ks) ^ r) * 4;
            const int q1 = ((2 * ks + 1) ^ r) * 4;
            unsigned af[4][4];
#pragma unroll
            for (int i = 0; i < 4; i++) {
                af[i][0] = __float_as_uint(As[a_b0[i] + q0]);
                af[i][1] = __float_as_uint(As[a_b8[i] + q0]);
                af[i][2] = __float_as_uint(As[a_b0[i] + q1]);
                af[i][3] = __float_as_uint(As[a_b8[i] + q1]);
            }
            const int kr0 = (ks * 8 + cq) * 128;
            const int kr1 = kr0 + 4 * 128;
            unsigned bf[4][2];
#pragma unroll
            for (int j = 0; j < 4; j++) {
                bf[j][0] = __float_as_uint(Bs[kr0 + b_n[j]]);
                bf[j][1] = __float_as_uint(Bs[kr1 + b_n[j]]);
            }
#pragma unroll
            for (int i = 0; i < 4; i++)
#pragma unroll
                for (int j = 0; j < 4; j++) {
                    asm volatile(
                        "mma.sync.aligned.m16n8k8.row.col.f32.tf32.tf32.f32 "
                        "{%0,%1,%2,%3}, {%4,%5,%6,%7}, {%8,%9}, {%0,%1,%2,%3};"
                        : "+f"(acc[i][j][0]), "+f"(acc[i][j][1]),
                          "+f"(acc[i][j][2]), "+f"(acc[i][j][3])
                        : "r"(af[i][0]), "r"(af[i][1]), "r"(af[i][2]), "r"(af[i][3]),
                          "r"(bf[j][0]), "r"(bf[j][1]));
                }
        }
    }

#pragma unroll
    for (int i = 0; i < 4; i++) {
        int row0 = rowBase + wr * 64 + i * 16 + r;
#pragma unroll
        for (int j = 0; j < 4; j++) {
            int col = colBase + wc * 32 + j * 8 + 2 * cq;
            *(float2*)&C[(size_t)row0 * NN + col] =
                make_float2(acc[i][j][0], acc[i][j][1]);
            *(float2*)&C[(size_t)(row0 + 8) * NN + col] =
                make_float2(acc[i][j][2], acc[i][j][3]);
        }
    }
}

__global__ __launch_bounds__(256, 2) void qkv_gemm() {
    extern __shared__ float smem[];
    const int z = blockIdx.z;
    const float* A = g_tf + OFF_X;
    const float* B = g_tf + OFF_WQ + (size_t)z * UNITS * UNITS;
    float* C = g_QKV + (size_t)z * NTOK * UNITS;
    gemm_body(A, B, C, UNITS, UNITS, smem, blockIdx.y * 128, blockIdx.x * 128);
}

__global__ __launch_bounds__(256, 2) void out_gemm(float* __restrict__ out) {
    extern __shared__ float smem[];
    gemm_body(g_O, g_tf + OFF_WO, out, UNITS, UNITS, smem,
              blockIdx.y * 128, blockIdx.x * 128);
}

// ---------------------------------------------------------------------------
// Block-sparse attention v3: one CTA per (block, head), 256 threads =
// 64 query slots x 4 dim-quarters. Chunked-8 online softmax (one rescale
// per 8 keys, 8-wide ILP on dots/exps). K/V rows padded: stride 80,
// quarter q at +20q -> conflict-free broadcast reads and aligned fills.
// Final partial chunk zero-padded with bias -2e9 (p underflows to exact 0).
// ---------------------------------------------------------------------------
#define KVSTR 80
#define QPAD  20

__global__ __launch_bounds__(256) void attn_kernel(const float* __restrict__ mask) {
    int b = blockIdx.x;
    int h = blockIdx.y;
    int m = g_cnt[b];
    if (m == 0) return;
    int off = g_off[b];

    const float* Q = g_QKV;
    const float* K = g_QKV + NTOK * UNITS;
    const float* V = g_QKV + 2 * NTOK * UNITS;

    __shared__ float Ks[CHK * KVSTR];
    __shared__ float Vs[CHK * KVSTR];
    __shared__ float bs[CHK];

    const int tid  = threadIdx.x;
    const int slot = tid >> 2;           // 0..63
    const int q    = tid & 3;            // dim quarter
    const int dg   = q * 16;             // global dim offset
    const int ds   = q * QPAD;           // smem quarter offset

    // loader geometry: row = tid>>3 (0..31), f4 = tid&7; handles f4 and f4+8
    const int lrow = tid >> 3;
    const int lf4  = tid & 7;
    const int d1   = lf4 * 4;            // dims 0..28
    const int d2   = 32 + lf4 * 4;       // dims 32..60
    const int s1   = (d1 >> 4) * QPAD + (d1 & 15);
    const int s2   = (d2 >> 4) * QPAD + (d2 & 15);

    for (int q0 = 0; q0 < m; q0 += 64) {
        int qi = q0 + slot;
        bool act = qi < m;
        int qt = act ? g_mem[off + qi] : g_mem[off];

        float qreg[16];
        {
            const float4* qp = (const float4*)(Q + (size_t)qt * UNITS + h * HDIM + dg);
#pragma unroll
            for (int i = 0; i < 4; i++) {
                float4 v = qp[i];
                qreg[4 * i + 0] = v.x; qreg[4 * i + 1] = v.y;
                qreg[4 * i + 2] = v.z; qreg[4 * i + 3] = v.w;
            }
        }

        float mx = -3e38f, sm = 0.f;
        float oacc[16];
#pragma unroll
        for (int d = 0; d < 16; d++) oacc[d] = 0.f;

        for (int k0 = 0; k0 < m; k0 += CHK) {
            int cn = min(CHK, m - k0);
            __syncthreads();
            {
                float4 kv1, kv2, vv1, vv2;
                if (lrow < cn) {
                    int tk = g_mem[off + k0 + lrow];
                    const float* kp = K + (size_t)tk * UNITS + h * HDIM;
                    const float* vp = V + (size_t)tk * UNITS + h * HDIM;
                    kv1 = *(const float4*)(kp + d1);
                    kv2 = *(const float4*)(kp + d2);
                    vv1 = *(const float4*)(vp + d1);
                    vv2 = *(const float4*)(vp + d2);
                    if (lf4 == 0) bs[lrow] = (1.0f - mask[tk]) * (-1e9f);
                } else {
                    kv1 = kv2 = vv1 = vv2 = make_float4(0.f, 0.f, 0.f, 0.f);
                    if (lf4 == 0) bs[lrow] = -2e9f;
                }
                *(float4*)&Ks[lrow * KVSTR + s1] = kv1;
                *(float4*)&Ks[lrow * KVSTR + s2] = kv2;
                *(float4*)&Vs[lrow * KVSTR + s1] = vv1;
                *(float4*)&Vs[lrow * KVSTR + s2] = vv2;
            }
            __syncthreads();

#pragma unroll
            for (int j0 = 0; j0 < CHK; j0 += 8) {
                float sreg[8];
#pragma unroll
                for (int jj = 0; jj < 8; jj++) {
                    const float4* kr = (const float4*)&Ks[(j0 + jj) * KVSTR + ds];
                    float p0 = 0.f;
#pragma unroll
                    for (int i = 0; i < 4; i++) {
                        float4 kv = kr[i];
                        p0 += qreg[4 * i + 0] * kv.x + qreg[4 * i + 1] * kv.y
                            + qreg[4 * i + 2] * kv.z + qreg[4 * i + 3] * kv.w;
                    }
                    sreg[jj] = p0;
                }
#pragma unroll
                for (int jj = 0; jj < 8; jj++) {
                    float s = sreg[jj];
                    s += __shfl_xor_sync(0xFFFFFFFFu, s, 1);
                    s += __shfl_xor_sync(0xFFFFFFFFu, s, 2);
                    sreg[jj] = s * 0.125f + bs[j0 + jj];
                }
                float cmax = sreg[0];
#pragma unroll
                for (int jj = 1; jj < 8; jj++) cmax = fmaxf(cmax, sreg[jj]);
                float nm = fmaxf(mx, cmax);
                float corr = __expf(mx - nm);
                sm *= corr;
#pragma unroll
                for (int d = 0; d < 16; d++) oacc[d] *= corr;
#pragma unroll
                for (int jj = 0; jj < 8; jj++) {
                    float p = __expf(sreg[jj] - nm);
                    sm += p;
                    const float4* vr = (const float4*)&Vs[(j0 + jj) * KVSTR + ds];
#pragma unroll
                    for (int i = 0; i < 4; i++) {
                        float4 vv = vr[i];
                        oacc[4 * i + 0] += p * vv.x;
                        oacc[4 * i + 1] += p * vv.y;
                        oacc[4 * i + 2] += p * vv.z;
                        oacc[4 * i + 3] += p * vv.w;
                    }
                }
                mx = nm;
            }
        }

        if (act) {
            float inv = 1.0f / sm;
            float* op = g_O + (size_t)qt * UNITS + h * HDIM + dg;
#pragma unroll
            for (int i = 0; i < 4; i++) {
                float4 v = make_float4(
                    __uint_as_float(f2tf32(oacc[4 * i + 0] * inv)),
                    __uint_as_float(f2tf32(oacc[4 * i + 1] * inv)),
                    __uint_as_float(f2tf32(oacc[4 * i + 2] * inv)),
                    __uint_as_float(f2tf32(oacc[4 * i + 3] * inv)));
                *(float4*)(op + 4 * i) = v;
            }
        }
    }
}

// ---------------------------------------------------------------------------
extern "C" void kernel_launch(void* const* d_in, const int* in_sizes, int n_in,
                              void* d_out, int out_size)
{
    const float* x    = (const float*)d_in[0];
    const float* Wq   = (const float*)d_in[1];
    const float* Wk   = (const float*)d_in[2];
    const float* Wv   = (const float*)d_in[3];
    const float* Wo   = (const float*)d_in[4];
    const float* mask = (const float*)d_in[5];
    const int*   ids  = (const int*)d_in[6];
    float* out = (float*)d_out;

    cudaFuncSetAttribute(qkv_gemm,
        cudaFuncAttributeMaxDynamicSharedMemorySize, 3 * STAGE_F * 4);
    cudaFuncSetAttribute(out_gemm,
        cudaFuncAttributeMaxDynamicSharedMemorySize, 3 * STAGE_F * 4);

    prep_kernel<<<7168, 256>>>(x, Wq, Wk, Wv, Wo);
    build_index_kernel<<<NBLK, 32>>>(ids);

    dim3 gq(UNITS / 128, NTOK / 128, 3);
    qkv_gemm<<<gq, 256, 3 * STAGE_F * 4>>>();

    attn_kernel<<<dim3(NBLK, NHEAD), 256>>>(mask);

    dim3 go(UNITS / 128, NTOK / 128);
    out_gemm<<<go, 256, 3 * STAGE_F * 4>>>(out);
}

// round 10
// speedup vs baseline: 1.7838x; 1.7838x over previous
#include <cuda_runtime.h>
#include <cuda_fp16.h>
#include <math.h>
#include <stdint.h>

#define NTOK  3072
#define UNITS 1024
#define NHEAD 16
#define HDIM  64
#define NBLK  64
#define CHK   32

// fp16 operand pool: [x | Wq | Wk | Wv | Wo]
#define OFF_X  0
#define OFF_WQ (NTOK * UNITS)
#define OFF_WK (OFF_WQ + UNITS * UNITS)
#define OFF_WV (OFF_WK + UNITS * UNITS)
#define OFF_WO (OFF_WV + UNITS * UNITS)
#define H_TOT  (OFF_WO + UNITS * UNITS)

__device__ __align__(16) __half g_h[H_TOT];
__device__ __align__(16) float  g_QKV[3 * NTOK * UNITS];
__device__ __align__(16) __half g_O[NTOK * UNITS];
__device__ int g_cnt[NBLK];
__device__ int g_off[NBLK];
__device__ int g_mem[NTOK];

__device__ __forceinline__ unsigned h2u(__half2 h) {
    return *reinterpret_cast<unsigned*>(&h);
}

// ---------------------------------------------------------------------------
// Prep: convert x + weights to fp16 once. 1835008 4-float groups.
// ---------------------------------------------------------------------------
__global__ __launch_bounds__(256) void prep_kernel(
    const float* __restrict__ x,  const float* __restrict__ Wq,
    const float* __restrict__ Wk, const float* __restrict__ Wv,
    const float* __restrict__ Wo)
{
    int i = blockIdx.x * 256 + threadIdx.x;
    const float* src; int base;
    if      (i <  786432) { src = x;  base = 0;       }
    else if (i < 1048576) { src = Wq; base = 786432;  }
    else if (i < 1310720) { src = Wk; base = 1048576; }
    else if (i < 1572864) { src = Wv; base = 1310720; }
    else                  { src = Wo; base = 1572864; }
    float4 v = ((const float4*)src)[i - base];
    __half2 h0 = __floats2half2_rn(v.x, v.y);
    __half2 h1 = __floats2half2_rn(v.z, v.w);
    ((uint2*)g_h)[i] = make_uint2(h2u(h0), h2u(h1));
}

// ---------------------------------------------------------------------------
// Parallel index build: one warp per block id, order-preserving ballot ranks.
// ---------------------------------------------------------------------------
__global__ __launch_bounds__(32) void build_index_kernel(const int* __restrict__ ids) {
    int b    = blockIdx.x;
    int lane = threadIdx.x;
    int cnt = 0, off = 0;
    for (int i0 = 0; i0 < NTOK; i0 += 32) {
        int id = ids[i0 + lane];
        unsigned meq = __ballot_sync(0xFFFFFFFFu, id == b);
        unsigned mlt = __ballot_sync(0xFFFFFFFFu, id < b);
        cnt += __popc(meq);
        off += __popc(mlt);
    }
    if (lane == 0) { g_cnt[b] = cnt; g_off[b] = off; }
    int run = off;
    unsigned lmask = (1u << lane) - 1u;
    for (int i0 = 0; i0 < NTOK; i0 += 32) {
        int id = ids[i0 + lane];
        unsigned meq = __ballot_sync(0xFFFFFFFFu, id == b);
        if (id == b) g_mem[run + __popc(meq & lmask)] = i0 + lane;
        run += __popc(meq);
    }
}

// ---------------------------------------------------------------------------
// FP16 GEMM, cp.async 3-stage + ldmatrix + mma.m16n8k16.
// C[M,N](fp32) = A[M,K](fp16) @ B[K,N](fp16). BM=BN=128, BK=32.
// 256 threads = 8 warps (2x4), warp tile 64x32.
// A stage: 128 rows x 80 B (32 halves + 16B pad) -> (5r+c)%8 distinct banksets.
// B stage: 32 rows x 272 B (128 halves + 16B pad) -> (17k+c)%8 = k%8 distinct.
// ---------------------------------------------------------------------------
#define A_STR   80
#define B_STR   272
#define A_STG   (128 * A_STR)          // 10240
#define B_STG   (32 * B_STR)           // 8704
#define STG_B   (A_STG + B_STG)        // 18944
#define NSTG    3
#define DYNSMEM (NSTG * STG_B)         // 56832

__device__ __forceinline__ void cp16g(uint32_t dst, const void* src) {
    asm volatile("cp.async.cg.shared.global [%0], [%1], 16;" :: "r"(dst), "l"(src));
}
__device__ __forceinline__ void ldmA4(unsigned* f, uint32_t a) {
    asm volatile("ldmatrix.sync.aligned.m8n8.x4.shared.b16 {%0,%1,%2,%3}, [%4];"
                 : "=r"(f[0]), "=r"(f[1]), "=r"(f[2]), "=r"(f[3]) : "r"(a));
}
__device__ __forceinline__ void ldmB4t(unsigned* f, uint32_t a) {
    asm volatile("ldmatrix.sync.aligned.m8n8.x4.trans.shared.b16 {%0,%1,%2,%3}, [%4];"
                 : "=r"(f[0]), "=r"(f[1]), "=r"(f[2]), "=r"(f[3]) : "r"(a));
}

__device__ __forceinline__ void gemm_body(
    const __half* __restrict__ A, const __half* __restrict__ B,
    float* __restrict__ C, int NN, int K,
    int rowBase, int colBase)
{
    extern __shared__ __align__(16) char smem[];
    const uint32_t sb = (uint32_t)__cvta_generic_to_shared(smem);

    const int t    = threadIdx.x;
    const int lane = t & 31;
    const int warp = t >> 5;
    const int wr   = warp >> 2;
    const int wc   = warp & 3;
    const int r    = lane >> 2;
    const int cq   = lane & 3;

    // cp.async A: thread t -> row t>>1, two 16B chunks c = (t&1)*2 + {0,1}
    const int arow = t >> 1;
    const int ac0  = (t & 1) * 2;
    const __half* Ag = A + (size_t)(rowBase + arow) * K + ac0 * 8;
    const uint32_t adst = (uint32_t)(arow * A_STR + ac0 * 16);
    // cp.async B: thread t -> k-row t>>3, two chunks c = (t&7)*2 + {0,1}
    const int bkr = t >> 3;
    const int bc0 = (t & 7) * 2;
    const __half* Bg = B + (size_t)bkr * NN + colBase + bc0 * 8;
    const uint32_t bdst = (uint32_t)(A_STG + bkr * B_STR + bc0 * 16);

    // ldmatrix addresses
    const int sel = lane >> 3;        // 0..3
    const int lrw = lane & 7;         // 0..7
    uint32_t aoff[4];
#pragma unroll
    for (int i = 0; i < 4; i++) {
        int m0 = wr * 64 + i * 16 + (sel & 1) * 8 + lrw;
        aoff[i] = (uint32_t)(m0 * A_STR + (sel >> 1) * 16);
    }
    uint32_t boff[2];
#pragma unroll
    for (int jp = 0; jp < 2; jp++) {
        int krow = (sel & 1) * 8 + lrw;
        int n0 = wc * 32 + jp * 16 + (sel >> 1) * 8;
        boff[jp] = (uint32_t)(A_STG + krow * B_STR + n0 * 2);
    }

    float acc[4][4][4];
#pragma unroll
    for (int i = 0; i < 4; i++)
#pragma unroll
        for (int j = 0; j < 4; j++)
#pragma unroll
            for (int e = 0; e < 4; e++) acc[i][j][e] = 0.f;

    const int nT = K / 32;

#pragma unroll
    for (int pt = 0; pt < 2; pt++) {
        uint32_t st = sb + pt * STG_B;
        const int ko = pt * 32;
        cp16g(st + adst,      Ag + ko);
        cp16g(st + adst + 16, Ag + ko + 8);
        cp16g(st + bdst,      Bg + (size_t)ko * NN);
        cp16g(st + bdst + 16, Bg + (size_t)ko * NN + 8);
        asm volatile("cp.async.commit_group;" ::: "memory");
    }

    for (int tt = 0; tt < nT; tt++) {
        asm volatile("cp.async.wait_group 1;" ::: "memory");
        __syncthreads();

        if (tt + 2 < nT) {
            uint32_t st = sb + ((tt + 2) % NSTG) * STG_B;
            const int ko = (tt + 2) * 32;
            cp16g(st + adst,      Ag + ko);
            cp16g(st + adst + 16, Ag + ko + 8);
            cp16g(st + bdst,      Bg + (size_t)ko * NN);
            cp16g(st + bdst + 16, Bg + (size_t)ko * NN + 8);
        }
        asm volatile("cp.async.commit_group;" ::: "memory");

        const uint32_t st = sb + (tt % NSTG) * STG_B;
#pragma unroll
        for (int ks = 0; ks < 2; ks++) {
            unsigned af[4][4];
#pragma unroll
            for (int i = 0; i < 4; i++)
                ldmA4(af[i], st + aoff[i] + ks * 32);
            unsigned bf[4][2];
#pragma unroll
            for (int jp = 0; jp < 2; jp++) {
                unsigned bt[4];
                ldmB4t(bt, st + boff[jp] + ks * 16 * B_STR);
                bf[2 * jp + 0][0] = bt[0]; bf[2 * jp + 0][1] = bt[1];
                bf[2 * jp + 1][0] = bt[2]; bf[2 * jp + 1][1] = bt[3];
            }
#pragma unroll
            for (int i = 0; i < 4; i++)
#pragma unroll
                for (int j = 0; j < 4; j++) {
                    asm volatile(
                        "mma.sync.aligned.m16n8k16.row.col.f32.f16.f16.f32 "
                        "{%0,%1,%2,%3}, {%4,%5,%6,%7}, {%8,%9}, {%0,%1,%2,%3};"
                        : "+f"(acc[i][j][0]), "+f"(acc[i][j][1]),
                          "+f"(acc[i][j][2]), "+f"(acc[i][j][3])
                        : "r"(af[i][0]), "r"(af[i][1]), "r"(af[i][2]), "r"(af[i][3]),
                          "r"(bf[j][0]), "r"(bf[j][1]));
                }
        }
    }

#pragma unroll
    for (int i = 0; i < 4; i++) {
        int row0 = rowBase + wr * 64 + i * 16 + r;
#pragma unroll
        for (int j = 0; j < 4; j++) {
            int col = colBase + wc * 32 + j * 8 + 2 * cq;
            *(float2*)&C[(size_t)row0 * NN + col] =
                make_float2(acc[i][j][0], acc[i][j][1]);
            *(float2*)&C[(size_t)(row0 + 8) * NN + col] =
                make_float2(acc[i][j][2], acc[i][j][3]);
        }
    }
}

__global__ __launch_bounds__(256, 2) void qkv_gemm() {
    const int z = blockIdx.z;
    gemm_body(g_h + OFF_X, g_h + OFF_WQ + (size_t)z * UNITS * UNITS,
              g_QKV + (size_t)z * NTOK * UNITS, UNITS, UNITS,
              blockIdx.y * 128, blockIdx.x * 128);
}
__global__ __launch_bounds__(256, 2) void out_gemm(float* __restrict__ out) {
    gemm_body(g_O, g_h + OFF_WO, out, UNITS, UNITS,
              blockIdx.y * 128, blockIdx.x * 128);
}

// ---------------------------------------------------------------------------
// Block-sparse attention (round-6 proven version; output stored fp16 for the
// fp16 out-GEMM). 128 threads = 64 slots x 2 halves.
// ---------------------------------------------------------------------------
#define KVSTR 68

__global__ __launch_bounds__(128) void attn_kernel(const float* __restrict__ mask) {
    int b = blockIdx.x;
    int h = blockIdx.y;
    int m = g_cnt[b];
    if (m == 0) return;
    int off = g_off[b];

    const float* Q = g_QKV;
    const float* K = g_QKV + NTOK * UNITS;
    const float* V = g_QKV + 2 * NTOK * UNITS;

    __shared__ float Ks[CHK * KVSTR];
    __shared__ float Vs[CHK * KVSTR];
    __shared__ float bs[CHK];

    const int tid   = threadIdx.x;
    const int slot  = tid >> 1;
    const int half  = tid & 1;
    const int dbase = half * 32;
    const int sbase = half * 36;

    for (int q0 = 0; q0 < m; q0 += 64) {
        int qi = q0 + slot;
        bool act = qi < m;
        int qt = act ? g_mem[off + qi] : g_mem[off];

        float qreg[32];
        {
            const float4* qp = (const float4*)(Q + (size_t)qt * UNITS + h * HDIM + dbase);
#pragma unroll
            for (int i = 0; i < 8; i++) {
                float4 v = qp[i];
                qreg[4 * i + 0] = v.x; qreg[4 * i + 1] = v.y;
                qreg[4 * i + 2] = v.z; qreg[4 * i + 3] = v.w;
            }
        }

        float mx = -3e38f, sm = 0.f;
        float oacc[32];
#pragma unroll
        for (int d = 0; d < 32; d++) oacc[d] = 0.f;

        for (int k0 = 0; k0 < m; k0 += CHK) {
            int cn = min(CHK, m - k0);
            __syncthreads();
            {
                int row = tid >> 2;
                int seg = (tid & 3) * 16;
                int adj = seg + ((seg >= 32) ? 4 : 0);
                if (row < cn) {
                    int tk = g_mem[off + k0 + row];
                    const float4* kp = (const float4*)(K + (size_t)tk * UNITS + h * HDIM + seg);
                    const float4* vp = (const float4*)(V + (size_t)tk * UNITS + h * HDIM + seg);
                    float4* kd = (float4*)&Ks[row * KVSTR + adj];
                    float4* vd = (float4*)&Vs[row * KVSTR + adj];
#pragma unroll
                    for (int i = 0; i < 4; i++) { kd[i] = kp[i]; vd[i] = vp[i]; }
                    if ((tid & 3) == 0)
                        bs[row] = (1.0f - mask[tk]) * (-1e9f);
                }
            }
            __syncthreads();

            for (int j = 0; j < cn; j++) {
                const float* kr = &Ks[j * KVSTR + sbase];
                float partial = 0.f;
#pragma unroll
                for (int d = 0; d < 32; d++) partial += qreg[d] * kr[d];
                float s = partial + __shfl_xor_sync(0xFFFFFFFFu, partial, 1);
                s = s * 0.125f + bs[j];

                if (s > mx) {
                    float corr = __expf(mx - s);
                    sm *= corr;
#pragma unroll
                    for (int d = 0; d < 32; d++) oacc[d] *= corr;
                    mx = s;
                }
                float p = __expf(s - mx);
                sm += p;
                const float* vr = &Vs[j * KVSTR + sbase];
#pragma unroll
                for (int d = 0; d < 32; d++) oacc[d] += p * vr[d];
            }
        }

        if (act) {
            float inv = 1.0f / sm;
            __half* op = g_O + (size_t)qt * UNITS + h * HDIM + dbase;
#pragma unroll
            for (int i = 0; i < 4; i++) {
                __half2 h0 = __floats2half2_rn(oacc[8 * i + 0] * inv, oacc[8 * i + 1] * inv);
                __half2 h1 = __floats2half2_rn(oacc[8 * i + 2] * inv, oacc[8 * i + 3] * inv);
                __half2 h2 = __floats2half2_rn(oacc[8 * i + 4] * inv, oacc[8 * i + 5] * inv);
                __half2 h3 = __floats2half2_rn(oacc[8 * i + 6] * inv, oacc[8 * i + 7] * inv);
                *(uint4*)(op + 8 * i) = make_uint4(h2u(h0), h2u(h1), h2u(h2), h2u(h3));
            }
        }
    }
}

// ---------------------------------------------------------------------------
extern "C" void kernel_launch(void* const* d_in, const int* in_sizes, int n_in,
                              void* d_out, int out_size)
{
    const float* x    = (const float*)d_in[0];
    const float* Wq   = (const float*)d_in[1];
    const float* Wk   = (const float*)d_in[2];
    const float* Wv   = (const float*)d_in[3];
    const float* Wo   = (const float*)d_in[4];
    const float* mask = (const float*)d_in[5];
    const int*   ids  = (const int*)d_in[6];
    float* out = (float*)d_out;

    cudaFuncSetAttribute(qkv_gemm,
        cudaFuncAttributeMaxDynamicSharedMemorySize, DYNSMEM);
    cudaFuncSetAttribute(out_gemm,
        cudaFuncAttributeMaxDynamicSharedMemorySize, DYNSMEM);

    prep_kernel<<<7168, 256>>>(x, Wq, Wk, Wv, Wo);
    build_index_kernel<<<NBLK, 32>>>(ids);

    dim3 gq(UNITS / 128, NTOK / 128, 3);
    qkv_gemm<<<gq, 256, DYNSMEM>>>();

    attn_kernel<<<dim3(NBLK, NHEAD), 128>>>(mask);

    dim3 go(UNITS / 128, NTOK / 128);
    out_gemm<<<go, 256, DYNSMEM>>>(out);
}